// round 17
// baseline (speedup 1.0000x reference)
#include <cuda_runtime.h>
#include <cuda_fp16.h>
#include <cuda_bf16.h>

// Problem shapes (fixed by the dataset)
constexpr int Bsz = 4096;   // batch rows
constexpr int Lh  = 128;    // sequence length
constexpr int Dd  = 64;     // feature dim
constexpr int NC  = 129;    // possible count values 0..128
constexpr int RPB = 4;      // batch rows per block -> grid 1024 = single wave
constexpr int TAIL = 16;    // positions kept: dropped mass e^-16 ~ 1.1e-7 rel
constexpr int CSMALL = 8;   // lut rows cached in shared (counts 0..7 typical)

// LUT: f(c)[d] = sum_e relu(c*W1[e]+b1[e]) * W2[e][d]
__device__ float g_lut[NC * Dd];

// 33 blocks x 256 threads; block handles 4 consecutive counts.
__global__ __launch_bounds__(256) void lut_kernel(
    const float* __restrict__ W1, const float* __restrict__ b1,
    const float* __restrict__ W2) {
    __shared__ float sW2[Dd * Dd];     // 16 KB, staged with float4
    __shared__ float sh[4][Dd];

    const int t  = threadIdx.x;
    const int ci = t >> 6;             // 0..3
    const int d  = t & 63;
    const int c  = blockIdx.x * 4 + ci;

    // stage W2 (coalesced float4, high MLP)
    const float4* w4 = reinterpret_cast<const float4*>(W2);
    float4* s4 = reinterpret_cast<float4*>(sW2);
#pragma unroll
    for (int k = t; k < Dd * Dd / 4; k += 256) s4[k] = w4[k];

    sh[ci][d] = fmaxf(fmaf((float)c, W1[d], b1[d]), 0.0f);
    __syncthreads();

    if (c < NC) {
        float acc = 0.0f;
#pragma unroll
        for (int e = 0; e < Dd; e++)
            acc = fmaf(sh[ci][e], sW2[e * Dd + d], acc);
        g_lut[c * Dd + d] = acc;
    }
}

// One block = 4 batch rows, 256 threads.
// Phase 1: ids -> shared as fp16 (ids<1000 exact in fp16); lut rows 0..7
//          staged to shared (counts are almost surely < 8).
// Phase 2: warp w of 8 -> (row=w>>1, query side=w&1). Lane j<16: count of
//          query j in SRC table; lane j+16: same query in DST table (the
//          reference sums the two channels into the same feature). fp16
//          SIMD2 compare-count: 1 instr / 2 elements on the FMA pipe.
//          Exp-weight folded into weighted count-histogram hw; first
//          toucher of hw[g][c] registers c in the nz list.
// Phase 3: out[side][b][d] = (sum_nz hw[c]*lut[c][d]) * (e-1) + 2*b2[d],
//          lut read from shared for c<8, global fallback otherwise.
__global__ __launch_bounds__(256, 8) void pool_kernel(
    const int* __restrict__ src_ids, const int* __restrict__ dst_ids,
    const float* __restrict__ b2, float* __restrict__ out)
{
    __shared__ alignas(16) __half s_idsh[RPB * 2 * Lh];  // 2 KB fp16 tables
    __shared__ float s_lut[CSMALL * Dd];                 // 2 KB lut cache
    __shared__ float s_hw[RPB * 2][NC + 3];              // weighted count hist
    __shared__ int   s_nz[RPB * 2][4 * TAIL];            // counts touched
    __shared__ int   s_nnz[RPB * 2];

    const int b0   = blockIdx.x * RPB;
    const int t    = threadIdx.x;
    const int side = t >> 7;
    const int i    = t & 127;

    // ---- phase 1: load ids (4 independent LDGs), publish as fp16 ----
    const int* ids = side ? dst_ids : src_ids;
#pragma unroll
    for (int r = 0; r < RPB; r++)
        s_idsh[(r * 2 + side) * Lh + i] = __int2half_rn(ids[(b0 + r) * Lh + i]);

    // stage lut rows 0..7 (first 512 floats of g_lut), coalesced float2
    {
        const float2* g2 = reinterpret_cast<const float2*>(g_lut);
        reinterpret_cast<float2*>(s_lut)[t] = g2[t];
    }

    // clear hw / nnz
    float* hwf = &s_hw[0][0];
#pragma unroll
    for (int k = t; k < RPB * 2 * (NC + 3); k += 256) hwf[k] = 0.0f;
    if (t < RPB * 2) s_nnz[t] = 0;
    __syncthreads();

    // ---- phase 2: fp16 SIMD count scan -> weighted count histograms ----
    {
        const int w    = t >> 5;          // warp 0..7
        const int lane = t & 31;
        const int r    = w >> 1;          // row this warp serves
        const int qh   = w & 1;           // query side (0=src,1=dst)
        const int tb   = lane >> 4;       // table this lane scans
        const int j    = lane & 15;       // tail query index 0..15

        const __half q = s_idsh[(r * 2 + qh) * Lh + (Lh - TAIL) + j];
        const __half2 qq = __half2half2(q);

        const uint4* tab =
            reinterpret_cast<const uint4*>(&s_idsh[(r * 2 + tb) * Lh]);
        __half2 a0 = __float2half2_rn(0.f), a1 = a0, a2 = a0, a3 = a0;
#pragma unroll
        for (int k = 0; k < Lh / 8; k++) {          // 16 x LDS.128 broadcast
            uint4 v = tab[k];
            a0 = __hadd2(a0, __heq2(*reinterpret_cast<__half2*>(&v.x), qq));
            a1 = __hadd2(a1, __heq2(*reinterpret_cast<__half2*>(&v.y), qq));
            a2 = __hadd2(a2, __heq2(*reinterpret_cast<__half2*>(&v.z), qq));
            a3 = __hadd2(a3, __heq2(*reinterpret_cast<__half2*>(&v.w), qq));
        }
        const __half2 acc = __hadd2(__hadd2(a0, a1), __hadd2(a2, a3));
        int c = (int)(__low2float(acc) + __high2float(acc));
        if (__half2float(q) == 0.0f) c = 0;         // padding forces count 0

        const float wgt = __expf((float)(j - TAIL)); // e^{pos-L}, pos=112+j
        const int g = r * 2 + qh;
        float o = atomicAdd(&s_hw[g][c], wgt);
        if (o == 0.0f) { int p = atomicAdd(&s_nnz[g], 1); s_nz[g][p] = c; }
    }
    __syncthreads();

    // ---- phase 3: sparse LUT contraction + epilogue (512 outputs) ----
    {
        const int d  = t & (Dd - 1);
        const float bb = 2.0f * b2[d];
#pragma unroll
        for (int half = 0; half < 2; half++) {
            const int g   = (t >> 6) + half * 4;   // row-side group 0..7
            const int r   = g >> 1;
            const int sd  = g & 1;
            const int nnz = s_nnz[g];
            float acc = 0.0f;
            for (int m = 0; m < nnz; m++) {
                int c = s_nz[g][m];                // broadcast LDS
                float lv = (c < CSMALL) ? s_lut[c * Dd + d]
                                        : g_lut[c * Dd + d];
                acc = fmaf(s_hw[g][c], lv, acc);
            }
            // 1 / w.sum() = (e-1)/(1 - e^-128) ~= e - 1
            out[sd * (Bsz * Dd) + (b0 + r) * Dd + d] =
                acc * 1.7182818284590452f + bb;
        }
    }
}

extern "C" void kernel_launch(void* const* d_in, const int* in_sizes, int n_in,
                              void* d_out, int out_size) {
    const int*   src = (const int*)d_in[0];
    const int*   dst = (const int*)d_in[1];
    const float* W1  = (const float*)d_in[2];
    const float* b1  = (const float*)d_in[3];
    const float* W2  = (const float*)d_in[4];
    const float* b2  = (const float*)d_in[5];
    float* out = (float*)d_out;

    lut_kernel<<<(NC + 3) / 4, 256>>>(W1, b1, W2);
    pool_kernel<<<Bsz / RPB, 256>>>(src, dst, b2, out);
}